// round 8
// baseline (speedup 1.0000x reference)
#include <cuda_runtime.h>
#include <math.h>
#include <float.h>

// Problem dims
#define T_SEQ 256
#define BATCH 512
#define IND   128
#define H1D   100
#define G1D   400     // 4*H1
#define H2D   128
#define G2D   512     // 4*H2
#define NC    19

typedef unsigned long long u64;

__device__ __forceinline__ void ffma2(u64 &d, u64 a, u64 b) {
    asm("fma.rn.f32x2 %0, %1, %2, %0;" : "+l"(d) : "l"(a), "l"(b));
}
__device__ __forceinline__ u64 pack2(float x, float y) {
    u64 r; asm("mov.b64 %0, {%1, %2};" : "=l"(r) : "f"(x), "f"(y)); return r;
}
__device__ __forceinline__ float2 unpk(u64 v) {
    float2 r; asm("mov.b64 {%0, %1}, %2;" : "=f"(r.x), "=f"(r.y) : "l"(v)); return r;
}
__device__ __forceinline__ float fsig(float a) {
    return __fdividef(1.f, 1.f + __expf(-a));
}

// ---------------- scratch ---------------------------------------------------
__device__ float g_zx1[256u*512u*400u];   // [(t,b)][G1]
__device__ float g_h1 [256u*512u*100u];   // [(t,b)][H1]
__device__ float g_zx2[256u*512u*512u];   // [(t,b)][G2]
__device__ float g_h2 [512u*128u];        // [B][H2]

// ---------------- feedforward GEMM: BM=128, BN=64, K-chunked (KS=64) --------
// 8x4 f32x2 outputs/thread: per k = 4 LDS.128 + 16 FFMA2 (80% FFMA2 issues).
#define BM 128
#define BN 64
#define KS 64
#define AP2 136   // padded As row (16B-aligned 8-float groups)

__global__ __launch_bounds__(256, 3)
void gemm_ff(const float* __restrict__ A, const float* __restrict__ Bw,
             const float* __restrict__ bias, float* __restrict__ C,
             int M, int N, int K, int mode)
{
    extern __shared__ __align__(16) float sm[];
    float* As = sm;                                    // [KS][AP2]
    u64*   Bs = reinterpret_cast<u64*>(sm + KS * AP2); // [KS][BN] dup-packed

    const int tid = threadIdx.x;
    const int m0 = blockIdx.x * BM;
    const int n0 = blockIdx.y * BN;
    const int tx = tid & 15, ty = tid >> 4;

    u64 acc2[4][4];
#pragma unroll
    for (int i = 0; i < 4; i++)
#pragma unroll
        for (int j = 0; j < 4; j++) acc2[i][j] = 0ull;

    for (int kc = 0; kc < K; kc += KS) {
        const int ks = (K - kc < KS) ? (K - kc) : KS;

        // load A chunk (transposed): As[k][mloc] = A[m0+mloc][kc+k]
        for (int idx = tid; idx < BM * ks; idx += 256) {
            int mloc = idx / ks;
            int k = idx - mloc * ks;
            int m = m0 + mloc;
            size_t arow;
            if (mode) { int t = m >> 9; int b = m & 511; arow = ((size_t)(b * T_SEQ + t)) * IND; }
            else      { arow = (size_t)m * K; }
            As[k * AP2 + mloc] = A[arow + kc + k];
        }
        // load B chunk dup-packed
        for (int idx = tid; idx < ks * BN; idx += 256) {
            int k = idx >> 6;
            int n = idx & 63;
            int gn = n0 + n;
            float v = (gn < N) ? Bw[(size_t)(kc + k) * N + gn] : 0.f;
            Bs[k * BN + n] = pack2(v, v);
        }
        __syncthreads();

#pragma unroll 4
        for (int k = 0; k < ks; ++k) {
            ulonglong2 a01 = *reinterpret_cast<const ulonglong2*>(&As[k * AP2 + ty * 8]);
            ulonglong2 a23 = *reinterpret_cast<const ulonglong2*>(&As[k * AP2 + ty * 8 + 4]);
            ulonglong2 b01 = *reinterpret_cast<const ulonglong2*>(&Bs[k * BN + tx * 4]);
            ulonglong2 b23 = *reinterpret_cast<const ulonglong2*>(&Bs[k * BN + tx * 4 + 2]);
            ffma2(acc2[0][0], a01.x, b01.x); ffma2(acc2[0][1], a01.x, b01.y);
            ffma2(acc2[0][2], a01.x, b23.x); ffma2(acc2[0][3], a01.x, b23.y);
            ffma2(acc2[1][0], a01.y, b01.x); ffma2(acc2[1][1], a01.y, b01.y);
            ffma2(acc2[1][2], a01.y, b23.x); ffma2(acc2[1][3], a01.y, b23.y);
            ffma2(acc2[2][0], a23.x, b01.x); ffma2(acc2[2][1], a23.x, b01.y);
            ffma2(acc2[2][2], a23.x, b23.x); ffma2(acc2[2][3], a23.x, b23.y);
            ffma2(acc2[3][0], a23.y, b01.x); ffma2(acc2[3][1], a23.y, b01.y);
            ffma2(acc2[3][2], a23.y, b23.x); ffma2(acc2[3][3], a23.y, b23.y);
        }
        __syncthreads();
    }

    const int n = n0 + tx * 4;
    float bn0 = 0.f, bn1 = 0.f, bn2 = 0.f, bn3 = 0.f;
    if (n + 3 < N) {
        bn0 = bias[n + 0]; bn1 = bias[n + 1];
        bn2 = bias[n + 2]; bn3 = bias[n + 3];
    }
#pragma unroll
    for (int p = 0; p < 4; p++) {
        float2 c0 = unpk(acc2[p][0]);
        float2 c1 = unpk(acc2[p][1]);
        float2 c2 = unpk(acc2[p][2]);
        float2 c3 = unpk(acc2[p][3]);
        int mA = m0 + ty * 8 + 2 * p;
        if (n + 3 < N) {
            *reinterpret_cast<float4*>(&C[(size_t)mA * N + n]) =
                make_float4(c0.x + bn0, c1.x + bn1, c2.x + bn2, c3.x + bn3);
            *reinterpret_cast<float4*>(&C[(size_t)(mA + 1) * N + n]) =
                make_float4(c0.y + bn0, c1.y + bn1, c2.y + bn2, c3.y + bn3);
        } else {
            float va[4] = {c0.x, c1.x, c2.x, c3.x};
            float vb[4] = {c0.y, c1.y, c2.y, c3.y};
#pragma unroll
            for (int jj = 0; jj < 4; jj++)
                if (n + jj < N) {
                    float bb = bias[n + jj];
                    C[(size_t)mA * N + n + jj] = va[jj] + bb;
                    C[(size_t)(mA + 1) * N + n + jj] = vb[jj] + bb;
                }
        }
    }
}

// ---------------- layer-1 scan: 256 threads, 2 columns/thread ---------------
#define U1REGJ 80
#define U1SMJ  20
#define H1P    104
#define ZSP    20
__global__ __launch_bounds__(256, 1)
void lstm_scan1(const float* __restrict__ zx, const float* __restrict__ U,
                float* __restrict__ hout)
{
    extern __shared__ __align__(16) float sm1[];
    float* U1sT = sm1;                       // [512 slots][U1SMJ]
    float* hT   = sm1 + 512 * U1SMJ;         // [2][4][H1P]
    float* zs   = hT + 2 * 4 * H1P;          // [128][ZSP]

    const int tid = threadIdx.x;
    const int j4 = tid >> 2;                 // 0..63
    const int k  = tid & 3;
    const int jA = (j4 < 50) ? j4 : 49;
    const int jB = jA + 50;
    const int colA = k * H1D + jA;
    const int colB = k * H1D + jB;
    const int b0 = blockIdx.x * 4;

    u64 UpA[U1REGJ / 2], UpB[U1REGJ / 2];
#pragma unroll
    for (int p = 0; p < U1REGJ / 2; ++p) {
        UpA[p] = pack2(U[(2 * p) * G1D + colA], U[(2 * p + 1) * G1D + colA]);
        UpB[p] = pack2(U[(2 * p) * G1D + colB], U[(2 * p + 1) * G1D + colB]);
    }
#pragma unroll
    for (int jj = 0; jj < U1SMJ; ++jj) {
        U1sT[tid * U1SMJ + jj]         = U[(U1REGJ + jj) * G1D + colA];
        U1sT[(256 + tid) * U1SMJ + jj] = U[(U1REGJ + jj) * G1D + colB];
    }
    for (int i = tid; i < 2 * 4 * H1P; i += 256) hT[i] = 0.f;

    float cA = 0.f, cB = 0.f;
    const float* zbA = zx + colA;
    const float* zbB = zx + colB;
    float zA0 = zbA[((size_t)0 * BATCH + b0 + 0) * G1D];
    float zA1 = zbA[((size_t)0 * BATCH + b0 + 1) * G1D];
    float zA2 = zbA[((size_t)0 * BATCH + b0 + 2) * G1D];
    float zA3 = zbA[((size_t)0 * BATCH + b0 + 3) * G1D];
    float zB0 = zbB[((size_t)0 * BATCH + b0 + 0) * G1D];
    float zB1 = zbB[((size_t)0 * BATCH + b0 + 1) * G1D];
    float zB2 = zbB[((size_t)0 * BATCH + b0 + 2) * G1D];
    float zB3 = zbB[((size_t)0 * BATCH + b0 + 3) * G1D];
    __syncthreads();

#pragma unroll 1
    for (int t = 0; t < T_SEQ; ++t) {
        int tn = (t + 1 < T_SEQ) ? (t + 1) : t;
        float nA0 = zbA[((size_t)tn * BATCH + b0 + 0) * G1D];
        float nA1 = zbA[((size_t)tn * BATCH + b0 + 1) * G1D];
        float nA2 = zbA[((size_t)tn * BATCH + b0 + 2) * G1D];
        float nA3 = zbA[((size_t)tn * BATCH + b0 + 3) * G1D];
        float nB0 = zbB[((size_t)tn * BATCH + b0 + 0) * G1D];
        float nB1 = zbB[((size_t)tn * BATCH + b0 + 1) * G1D];
        float nB2 = zbB[((size_t)tn * BATCH + b0 + 2) * G1D];
        float nB3 = zbB[((size_t)tn * BATCH + b0 + 3) * G1D];

        const float* hp = hT + (t & 1) * (4 * H1P);
        u64 aA0 = 0ull, aA1 = 0ull, aA2 = 0ull, aA3 = 0ull;
        u64 aB0 = 0ull, aB1 = 0ull, aB2 = 0ull, aB3 = 0ull;
#pragma unroll
        for (int p4 = 0; p4 < U1REGJ / 4; ++p4) {
            int j0 = 4 * p4;
            ulonglong2 h0 = *reinterpret_cast<const ulonglong2*>(&hp[0 * H1P + j0]);
            ulonglong2 h1 = *reinterpret_cast<const ulonglong2*>(&hp[1 * H1P + j0]);
            ulonglong2 h2 = *reinterpret_cast<const ulonglong2*>(&hp[2 * H1P + j0]);
            ulonglong2 h3 = *reinterpret_cast<const ulonglong2*>(&hp[3 * H1P + j0]);
            u64 ua = UpA[2 * p4], ub = UpA[2 * p4 + 1];
            u64 va = UpB[2 * p4], vb = UpB[2 * p4 + 1];
            ffma2(aA0, h0.x, ua); ffma2(aA0, h0.y, ub);
            ffma2(aA1, h1.x, ua); ffma2(aA1, h1.y, ub);
            ffma2(aA2, h2.x, ua); ffma2(aA2, h2.y, ub);
            ffma2(aA3, h3.x, ua); ffma2(aA3, h3.y, ub);
            ffma2(aB0, h0.x, va); ffma2(aB0, h0.y, vb);
            ffma2(aB1, h1.x, va); ffma2(aB1, h1.y, vb);
            ffma2(aB2, h2.x, va); ffma2(aB2, h2.y, vb);
            ffma2(aB3, h3.x, va); ffma2(aB3, h3.y, vb);
        }
#pragma unroll
        for (int q = 0; q < U1SMJ / 4; ++q) {
            int j0 = U1REGJ + 4 * q;
            ulonglong2 uA = *reinterpret_cast<const ulonglong2*>(&U1sT[tid * U1SMJ + 4 * q]);
            ulonglong2 uB = *reinterpret_cast<const ulonglong2*>(&U1sT[(256 + tid) * U1SMJ + 4 * q]);
            ulonglong2 h0 = *reinterpret_cast<const ulonglong2*>(&hp[0 * H1P + j0]);
            ulonglong2 h1 = *reinterpret_cast<const ulonglong2*>(&hp[1 * H1P + j0]);
            ulonglong2 h2 = *reinterpret_cast<const ulonglong2*>(&hp[2 * H1P + j0]);
            ulonglong2 h3 = *reinterpret_cast<const ulonglong2*>(&hp[3 * H1P + j0]);
            ffma2(aA0, h0.x, uA.x); ffma2(aA0, h0.y, uA.y);
            ffma2(aA1, h1.x, uA.x); ffma2(aA1, h1.y, uA.y);
            ffma2(aA2, h2.x, uA.x); ffma2(aA2, h2.y, uA.y);
            ffma2(aA3, h3.x, uA.x); ffma2(aA3, h3.y, uA.y);
            ffma2(aB0, h0.x, uB.x); ffma2(aB0, h0.y, uB.y);
            ffma2(aB1, h1.x, uB.x); ffma2(aB1, h1.y, uB.y);
            ffma2(aB2, h2.x, uB.x); ffma2(aB2, h2.y, uB.y);
            ffma2(aB3, h3.x, uB.x); ffma2(aB3, h3.y, uB.y);
        }
        float2 sA0 = unpk(aA0), sA1 = unpk(aA1), sA2 = unpk(aA2), sA3 = unpk(aA3);
        float2 sB0 = unpk(aB0), sB1 = unpk(aB1), sB2 = unpk(aB2), sB3 = unpk(aB3);
        float vA0 = sA0.x + sA0.y + zA0;
        float vA1 = sA1.x + sA1.y + zA1;
        float vA2 = sA2.x + sA2.y + zA2;
        float vA3 = sA3.x + sA3.y + zA3;
        float vB0 = sB0.x + sB0.y + zB0;
        float vB1 = sB1.x + sB1.y + zB1;
        float vB2 = sB2.x + sB2.y + zB2;
        float vB3 = sB3.x + sB3.y + zB3;
        if (k == 2) {
            vA0 = fmaxf(vA0, 0.f); vA1 = fmaxf(vA1, 0.f);
            vA2 = fmaxf(vA2, 0.f); vA3 = fmaxf(vA3, 0.f);
            vB0 = fmaxf(vB0, 0.f); vB1 = fmaxf(vB1, 0.f);
            vB2 = fmaxf(vB2, 0.f); vB3 = fmaxf(vB3, 0.f);
        } else {
            vA0 = fsig(vA0); vA1 = fsig(vA1); vA2 = fsig(vA2); vA3 = fsig(vA3);
            vB0 = fsig(vB0); vB1 = fsig(vB1); vB2 = fsig(vB2); vB3 = fsig(vB3);
        }
        *reinterpret_cast<float4*>(&zs[jA * ZSP + k * 4]) = make_float4(vA0, vA1, vA2, vA3);
        *reinterpret_cast<float4*>(&zs[jB * ZSP + k * 4]) = make_float4(vB0, vB1, vB2, vB3);
        __syncwarp();
        {
            float gi = zs[jA * ZSP + 0  + k];
            float gf = zs[jA * ZSP + 4  + k];
            float gg = zs[jA * ZSP + 8  + k];
            float go = zs[jA * ZSP + 12 + k];
            cA = fmaf(gf, cA, gi * gg);
            float h = go * fmaxf(cA, 0.f);
            hT[(1 - (t & 1)) * (4 * H1P) + k * H1P + jA] = h;
            if (j4 < 50) hout[((size_t)t * BATCH + b0 + k) * H1D + jA] = h;
        }
        {
            float gi = zs[jB * ZSP + 0  + k];
            float gf = zs[jB * ZSP + 4  + k];
            float gg = zs[jB * ZSP + 8  + k];
            float go = zs[jB * ZSP + 12 + k];
            cB = fmaf(gf, cB, gi * gg);
            float h = go * fmaxf(cB, 0.f);
            hT[(1 - (t & 1)) * (4 * H1P) + k * H1P + jB] = h;
            if (j4 < 50) hout[((size_t)t * BATCH + b0 + k) * H1D + jB] = h;
        }
        zA0 = nA0; zA1 = nA1; zA2 = nA2; zA3 = nA3;
        zB0 = nB0; zB1 = nB1; zB2 = nB2; zB3 = nB3;
        __syncthreads();
    }
}

// ---------------- layer-2 scan (R6-proven): 256 threads, 2 cols/thread ------
#define U2REGJ 80
#define U2SMJ  48
#define U2P    52
__global__ __launch_bounds__(256, 1)
void lstm_scan2(const float* __restrict__ zx, const float* __restrict__ U,
                float* __restrict__ h2out)
{
    extern __shared__ __align__(16) float sm2[];
    float* U2sT = sm2;                       // [512 slots][U2P]
    float* hT   = sm2 + 512 * U2P;           // [2][4][H2D]
    float* zs   = hT + 2 * 4 * H2D;          // [128][ZSP]

    const int tid = threadIdx.x;
    const int j  = tid >> 2;        // 0..63
    const int k  = tid & 3;
    const int jA = j, jB = j + 64;
    const int colA = k * H2D + jA;
    const int colB = k * H2D + jB;
    const int b0 = blockIdx.x * 4;

    u64 UpA[U2REGJ / 2], UpB[U2REGJ / 2];
#pragma unroll
    for (int p = 0; p < U2REGJ / 2; ++p) {
        UpA[p] = pack2(U[(2 * p) * G2D + colA], U[(2 * p + 1) * G2D + colA]);
        UpB[p] = pack2(U[(2 * p) * G2D + colB], U[(2 * p + 1) * G2D + colB]);
    }
    for (int idx = tid; idx < U2SMJ * G2D; idx += 256) {
        int r = idx >> 9;
        int cc = idx & 511;
        int jj = cc & 127, kk = cc >> 7;
        int slot = (jj < 64) ? (4 * jj + kk) : (256 + 4 * (jj - 64) + kk);
        U2sT[slot * U2P + r] = U[(size_t)(U2REGJ + r) * G2D + cc];
    }
    for (int i = tid; i < 2 * 4 * H2D; i += 256) hT[i] = 0.f;

    float cA = 0.f, cB = 0.f;
    const float* zbA = zx + colA;
    const float* zbB = zx + colB;
    float zA0 = zbA[((size_t)0 * BATCH + b0 + 0) * G2D];
    float zA1 = zbA[((size_t)0 * BATCH + b0 + 1) * G2D];
    float zA2 = zbA[((size_t)0 * BATCH + b0 + 2) * G2D];
    float zA3 = zbA[((size_t)0 * BATCH + b0 + 3) * G2D];
    float zB0 = zbB[((size_t)0 * BATCH + b0 + 0) * G2D];
    float zB1 = zbB[((size_t)0 * BATCH + b0 + 1) * G2D];
    float zB2 = zbB[((size_t)0 * BATCH + b0 + 2) * G2D];
    float zB3 = zbB[((size_t)0 * BATCH + b0 + 3) * G2D];
    __syncthreads();

#pragma unroll 1
    for (int t = 0; t < T_SEQ; ++t) {
        int tn = (t + 1 < T_SEQ) ? (t + 1) : t;
        float nA0 = zbA[((size_t)tn * BATCH + b0 + 0) * G2D];
        float nA1 = zbA[((size_t)tn * BATCH + b0 + 1) * G2D];
        float nA2 = zbA[((size_t)tn * BATCH + b0 + 2) * G2D];
        float nA3 = zbA[((size_t)tn * BATCH + b0 + 3) * G2D];
        float nB0 = zbB[((size_t)tn * BATCH + b0 + 0) * G2D];
        float nB1 = zbB[((size_t)tn * BATCH + b0 + 1) * G2D];
        float nB2 = zbB[((size_t)tn * BATCH + b0 + 2) * G2D];
        float nB3 = zbB[((size_t)tn * BATCH + b0 + 3) * G2D];

        const float* hp = hT + (t & 1) * (4 * H2D);
        u64 aA0 = 0ull, aA1 = 0ull, aA2 = 0ull, aA3 = 0ull;
        u64 aB0 = 0ull, aB1 = 0ull, aB2 = 0ull, aB3 = 0ull;
#pragma unroll
        for (int p4 = 0; p4 < U2REGJ / 4; ++p4) {
            int j0 = 4 * p4;
            ulonglong2 h0 = *reinterpret_cast<const ulonglong2*>(&hp[0 * H2D + j0]);
            ulonglong2 h1 = *reinterpret_cast<const ulonglong2*>(&hp[1 * H2D + j0]);
            ulonglong2 h2 = *reinterpret_cast<const ulonglong2*>(&hp[2 * H2D + j0]);
            ulonglong2 h3 = *reinterpret_cast<const ulonglong2*>(&hp[3 * H2D + j0]);
            u64 ua = UpA[2 * p4], ub = UpA[2 * p4 + 1];
            u64 va = UpB[2 * p4], vb = UpB[2 * p4 + 1];
            ffma2(aA0, h0.x, ua); ffma2(aA0, h0.y, ub);
            ffma2(aA1, h1.x, ua); ffma2(aA1, h1.y, ub);
            ffma2(aA2, h2.x, ua); ffma2(aA2, h2.y, ub);
            ffma2(aA3, h3.x, ua); ffma2(aA3, h3.y, ub);
            ffma2(aB0, h0.x, va); ffma2(aB0, h0.y, vb);
            ffma2(aB1, h1.x, va); ffma2(aB1, h1.y, vb);
            ffma2(aB2, h2.x, va); ffma2(aB2, h2.y, vb);
            ffma2(aB3, h3.x, va); ffma2(aB3, h3.y, vb);
        }
#pragma unroll
        for (int q = 0; q < U2SMJ / 4; ++q) {
            int j0 = U2REGJ + 4 * q;
            ulonglong2 uA = *reinterpret_cast<const ulonglong2*>(&U2sT[tid * U2P + 4 * q]);
            ulonglong2 uB = *reinterpret_cast<const ulonglong2*>(&U2sT[(256 + tid) * U2P + 4 * q]);
            ulonglong2 h0 = *reinterpret_cast<const ulonglong2*>(&hp[0 * H2D + j0]);
            ulonglong2 h1 = *reinterpret_cast<const ulonglong2*>(&hp[1 * H2D + j0]);
            ulonglong2 h2 = *reinterpret_cast<const ulonglong2*>(&hp[2 * H2D + j0]);
            ulonglong2 h3 = *reinterpret_cast<const ulonglong2*>(&hp[3 * H2D + j0]);
            ffma2(aA0, h0.x, uA.x); ffma2(aA0, h0.y, uA.y);
            ffma2(aA1, h1.x, uA.x); ffma2(aA1, h1.y, uA.y);
            ffma2(aA2, h2.x, uA.x); ffma2(aA2, h2.y, uA.y);
            ffma2(aA3, h3.x, uA.x); ffma2(aA3, h3.y, uA.y);
            ffma2(aB0, h0.x, uB.x); ffma2(aB0, h0.y, uB.y);
            ffma2(aB1, h1.x, uB.x); ffma2(aB1, h1.y, uB.y);
            ffma2(aB2, h2.x, uB.x); ffma2(aB2, h2.y, uB.y);
            ffma2(aB3, h3.x, uB.x); ffma2(aB3, h3.y, uB.y);
        }
        float2 sA0 = unpk(aA0), sA1 = unpk(aA1), sA2 = unpk(aA2), sA3 = unpk(aA3);
        float2 sB0 = unpk(aB0), sB1 = unpk(aB1), sB2 = unpk(aB2), sB3 = unpk(aB3);
        float vA0 = sA0.x + sA0.y + zA0;
        float vA1 = sA1.x + sA1.y + zA1;
        float vA2 = sA2.x + sA2.y + zA2;
        float vA3 = sA3.x + sA3.y + zA3;
        float vB0 = sB0.x + sB0.y + zB0;
        float vB1 = sB1.x + sB1.y + zB1;
        float vB2 = sB2.x + sB2.y + zB2;
        float vB3 = sB3.x + sB3.y + zB3;
        if (k == 2) {
            vA0 = fmaxf(vA0, 0.f); vA1 = fmaxf(vA1, 0.f);
            vA2 = fmaxf(vA2, 0.f); vA3 = fmaxf(vA3, 0.f);
            vB0 = fmaxf(vB0, 0.f); vB1 = fmaxf(vB1, 0.f);
            vB2 = fmaxf(vB2, 0.f); vB3 = fmaxf(vB3, 0.f);
        } else {
            vA0 = fsig(vA0); vA1 = fsig(vA1); vA2 = fsig(vA2); vA3 = fsig(vA3);
            vB0 = fsig(vB0); vB1 = fsig(vB1); vB2 = fsig(vB2); vB3 = fsig(vB3);
        }
        *reinterpret_cast<float4*>(&zs[jA * ZSP + k * 4]) = make_float4(vA0, vA1, vA2, vA3);
        *reinterpret_cast<float4*>(&zs[jB * ZSP + k * 4]) = make_float4(vB0, vB1, vB2, vB3);
        __syncwarp();
        {
            float gi = zs[jA * ZSP + 0  + k];
            float gf = zs[jA * ZSP + 4  + k];
            float gg = zs[jA * ZSP + 8  + k];
            float go = zs[jA * ZSP + 12 + k];
            cA = fmaf(gf, cA, gi * gg);
            float h = go * fmaxf(cA, 0.f);
            hT[(1 - (t & 1)) * (4 * H2D) + k * H2D + jA] = h;
            if (t == T_SEQ - 1) h2out[(b0 + k) * H2D + jA] = h;
        }
        {
            float gi = zs[jB * ZSP + 0  + k];
            float gf = zs[jB * ZSP + 4  + k];
            float gg = zs[jB * ZSP + 8  + k];
            float go = zs[jB * ZSP + 12 + k];
            cB = fmaf(gf, cB, gi * gg);
            float h = go * fmaxf(cB, 0.f);
            hT[(1 - (t & 1)) * (4 * H2D) + k * H2D + jB] = h;
            if (t == T_SEQ - 1) h2out[(b0 + k) * H2D + jB] = h;
        }
        zA0 = nA0; zA1 = nA1; zA2 = nA2; zA3 = nA3;
        zB0 = nB0; zB1 = nB1; zB2 = nB2; zB3 = nB3;
        __syncthreads();
    }
}

// ---------------- dense head + softmax -------------------------------------
__global__ void head_kernel(const float* __restrict__ h2, const float* __restrict__ Wd,
                            const float* __restrict__ bd, float* __restrict__ out)
{
    __shared__ float hsh[H2D];
    const int b = blockIdx.x;
    const int lane = threadIdx.x;
    for (int j = lane; j < H2D; j += 32) hsh[j] = h2[b * H2D + j];
    __syncthreads();

    float acc = 0.f;
    if (lane < NC) {
        acc = bd[lane];
#pragma unroll
        for (int j = 0; j < H2D; ++j) acc = fmaf(hsh[j], Wd[j * NC + lane], acc);
    }
    float v = (lane < NC) ? acc : -FLT_MAX;
#pragma unroll
    for (int off = 16; off > 0; off >>= 1)
        v = fmaxf(v, __shfl_xor_sync(0xffffffffu, v, off));
    float e = (lane < NC) ? expf(acc - v) : 0.f;
    float s = e;
#pragma unroll
    for (int off = 16; off > 0; off >>= 1)
        s += __shfl_xor_sync(0xffffffffu, s, off);
    if (lane < NC) out[b * NC + lane] = e / s;
}

// ---------------- launch ----------------------------------------------------
extern "C" void kernel_launch(void* const* d_in, const int* in_sizes, int n_in,
                              void* d_out, int out_size)
{
    const float* x  = (const float*)d_in[0];
    const float* W1 = (const float*)d_in[1];
    const float* U1 = (const float*)d_in[2];
    const float* b1 = (const float*)d_in[3];
    const float* W2 = (const float*)d_in[4];
    const float* U2 = (const float*)d_in[5];
    const float* b2 = (const float*)d_in[6];
    const float* Wd = (const float*)d_in[7];
    const float* bd = (const float*)d_in[8];
    float* out = (float*)d_out;

    const int gemm_smem  = KS * AP2 * 4 + KS * BN * 8;                     // 67584
    const int scan1_smem = (512 * U1SMJ + 2 * 4 * H1P + 128 * ZSP) * 4;    // 54528
    const int scan2_smem = (512 * U2P + 2 * 4 * H2D + 128 * ZSP) * 4;      // 120832
    cudaFuncSetAttribute(gemm_ff,    cudaFuncAttributeMaxDynamicSharedMemorySize, gemm_smem);
    cudaFuncSetAttribute(lstm_scan1, cudaFuncAttributeMaxDynamicSharedMemorySize, scan1_smem);
    cudaFuncSetAttribute(lstm_scan2, cudaFuncAttributeMaxDynamicSharedMemorySize, scan2_smem);

    float *zx1p, *h1p, *zx2p, *h2p;
    cudaGetSymbolAddress((void**)&zx1p, g_zx1);
    cudaGetSymbolAddress((void**)&h1p,  g_h1);
    cudaGetSymbolAddress((void**)&zx2p, g_zx2);
    cudaGetSymbolAddress((void**)&h2p,  g_h2);

    const int M = T_SEQ * BATCH;

    gemm_ff<<<dim3(M / BM, (G1D + BN - 1) / BN), 256, gemm_smem>>>(
        x, W1, b1, zx1p, M, G1D, IND, 1);

    lstm_scan1<<<BATCH / 4, 256, scan1_smem>>>(zx1p, U1, h1p);

    gemm_ff<<<dim3(M / BM, G2D / BN), 256, gemm_smem>>>(
        h1p, W2, b2, zx2p, M, G2D, H1D, 0);

    lstm_scan2<<<BATCH / 4, 256, scan2_smem>>>(zx2p, U2, h2p);

    head_kernel<<<BATCH, 32>>>(h2p, Wd, bd, out);
}

// round 9
// speedup vs baseline: 1.2948x; 1.2948x over previous
#include <cuda_runtime.h>
#include <math.h>
#include <float.h>

// Problem dims
#define T_SEQ 256
#define BATCH 512
#define IND   128
#define H1D   100
#define G1D   400     // 4*H1
#define H2D   128
#define G2D   512     // 4*H2
#define NC    19

typedef unsigned long long u64;

__device__ __forceinline__ void ffma2(u64 &d, u64 a, u64 b) {
    asm("fma.rn.f32x2 %0, %1, %2, %0;" : "+l"(d) : "l"(a), "l"(b));
}
__device__ __forceinline__ u64 pack2(float x, float y) {
    u64 r; asm("mov.b64 %0, {%1, %2};" : "=l"(r) : "f"(x), "f"(y)); return r;
}
__device__ __forceinline__ float2 unpk(u64 v) {
    float2 r; asm("mov.b64 {%0, %1}, %2;" : "=f"(r.x), "=f"(r.y) : "l"(v)); return r;
}
__device__ __forceinline__ float fsig(float a) {
    return __fdividef(1.f, 1.f + __expf(-a));
}

// ---------------- scratch ---------------------------------------------------
__device__ float g_zx1[256u*512u*400u];   // [(t,b)][G1]
__device__ float g_h1 [256u*512u*100u];   // [(t,b)][H1]
__device__ float g_zx2[256u*512u*512u];   // [(t,b)][G2]
__device__ float g_h2 [512u*128u];        // [B][H2]

// ---------------- feedforward GEMM: A-tile resident, n-loop inside ----------
// Block owns one 64-row A tile (loaded ONCE); loops over all n-tiles with the
// R4-proven inner loop. A DRAM traffic / LDG latency amortized 7-8x.
#define BM 64
#define BN 64
#define KMAX 128
#define AP 68

__global__ __launch_bounds__(256, 3)
void gemm_ff(const float* __restrict__ A, const float* __restrict__ Bw,
             const float* __restrict__ bias, float* __restrict__ C,
             int M, int N, int K, int mode)
{
    extern __shared__ float sm[];
    float* As = sm;                 // [KMAX][AP]  transposed A tile
    float* Bs = sm + KMAX * AP;     // [KMAX][BN]

    const int tid = threadIdx.x;
    const int m0 = blockIdx.x * BM;
    const int tx = tid & 15, ty = tid >> 4;

    // load A tile once
    for (int idx = tid; idx < BM * K; idx += 256) {
        int mloc = idx / K;
        int k = idx - mloc * K;
        int m = m0 + mloc;
        size_t arow;
        if (mode) { int t = m >> 9; int b = m & 511; arow = ((size_t)(b * T_SEQ + t)) * IND; }
        else      { arow = (size_t)m * K; }
        As[k * AP + mloc] = A[arow + k];
    }

    const int ntiles = (N + BN - 1) / BN;
    for (int nt = 0; nt < ntiles; ++nt) {
        const int n0 = nt * BN;
        if (nt > 0) __syncthreads();     // previous compute done before Bs overwrite
        for (int idx = tid; idx < K * BN; idx += 256) {
            int k = idx >> 6;
            int n = idx & 63;
            int gn = n0 + n;
            Bs[k * BN + n] = (gn < N) ? Bw[(size_t)k * N + gn] : 0.f;
        }
        __syncthreads();                 // Bs (and As on first iter) ready

        u64 acc2[2][4];
#pragma unroll
        for (int i = 0; i < 2; i++)
#pragma unroll
            for (int j = 0; j < 4; j++) acc2[i][j] = 0ull;

#pragma unroll 4
        for (int k = 0; k < K; ++k) {
            ulonglong2 av = *reinterpret_cast<const ulonglong2*>(&As[k * AP + ty * 4]);
            float4 bv = *reinterpret_cast<const float4*>(&Bs[k * BN + tx * 4]);
            u64 b0 = pack2(bv.x, bv.x);
            u64 b1 = pack2(bv.y, bv.y);
            u64 b2 = pack2(bv.z, bv.z);
            u64 b3 = pack2(bv.w, bv.w);
            ffma2(acc2[0][0], av.x, b0); ffma2(acc2[0][1], av.x, b1);
            ffma2(acc2[0][2], av.x, b2); ffma2(acc2[0][3], av.x, b3);
            ffma2(acc2[1][0], av.y, b0); ffma2(acc2[1][1], av.y, b1);
            ffma2(acc2[1][2], av.y, b2); ffma2(acc2[1][3], av.y, b3);
        }

        float accf[4][4];
#pragma unroll
        for (int j = 0; j < 4; j++) {
            float2 p = unpk(acc2[0][j]);
            float2 q = unpk(acc2[1][j]);
            accf[0][j] = p.x; accf[1][j] = p.y;
            accf[2][j] = q.x; accf[3][j] = q.y;
        }

#pragma unroll
        for (int i = 0; i < 4; i++) {
            int m = m0 + ty * 4 + i;
            int n = n0 + tx * 4;
            float* cp = &C[(size_t)m * N + n];
            if (n + 3 < N) {
                float4 v;
                v.x = accf[i][0] + bias[n + 0];
                v.y = accf[i][1] + bias[n + 1];
                v.z = accf[i][2] + bias[n + 2];
                v.w = accf[i][3] + bias[n + 3];
                *reinterpret_cast<float4*>(cp) = v;
            } else {
#pragma unroll
                for (int j = 0; j < 4; j++)
                    if (n + j < N) cp[j] = accf[i][j] + bias[n + j];
            }
        }
    }
}

// ---------------- layer-1 scan: 256 threads, 2 columns/thread (R7) ----------
#define U1REGJ 80
#define U1SMJ  20
#define H1P    104
#define ZSP    20
__global__ __launch_bounds__(256, 1)
void lstm_scan1(const float* __restrict__ zx, const float* __restrict__ U,
                float* __restrict__ hout)
{
    extern __shared__ __align__(16) float sm1[];
    float* U1sT = sm1;                       // [512 slots][U1SMJ]
    float* hT   = sm1 + 512 * U1SMJ;         // [2][4][H1P]
    float* zs   = hT + 2 * 4 * H1P;          // [128][ZSP]

    const int tid = threadIdx.x;
    const int j4 = tid >> 2;                 // 0..63
    const int k  = tid & 3;
    const int jA = (j4 < 50) ? j4 : 49;
    const int jB = jA + 50;
    const int colA = k * H1D + jA;
    const int colB = k * H1D + jB;
    const int b0 = blockIdx.x * 4;

    u64 UpA[U1REGJ / 2], UpB[U1REGJ / 2];
#pragma unroll
    for (int p = 0; p < U1REGJ / 2; ++p) {
        UpA[p] = pack2(U[(2 * p) * G1D + colA], U[(2 * p + 1) * G1D + colA]);
        UpB[p] = pack2(U[(2 * p) * G1D + colB], U[(2 * p + 1) * G1D + colB]);
    }
#pragma unroll
    for (int jj = 0; jj < U1SMJ; ++jj) {
        U1sT[tid * U1SMJ + jj]         = U[(U1REGJ + jj) * G1D + colA];
        U1sT[(256 + tid) * U1SMJ + jj] = U[(U1REGJ + jj) * G1D + colB];
    }
    for (int i = tid; i < 2 * 4 * H1P; i += 256) hT[i] = 0.f;

    float cA = 0.f, cB = 0.f;
    const float* zbA = zx + colA;
    const float* zbB = zx + colB;
    float zA0 = zbA[((size_t)0 * BATCH + b0 + 0) * G1D];
    float zA1 = zbA[((size_t)0 * BATCH + b0 + 1) * G1D];
    float zA2 = zbA[((size_t)0 * BATCH + b0 + 2) * G1D];
    float zA3 = zbA[((size_t)0 * BATCH + b0 + 3) * G1D];
    float zB0 = zbB[((size_t)0 * BATCH + b0 + 0) * G1D];
    float zB1 = zbB[((size_t)0 * BATCH + b0 + 1) * G1D];
    float zB2 = zbB[((size_t)0 * BATCH + b0 + 2) * G1D];
    float zB3 = zbB[((size_t)0 * BATCH + b0 + 3) * G1D];
    __syncthreads();

#pragma unroll 1
    for (int t = 0; t < T_SEQ; ++t) {
        int tn = (t + 1 < T_SEQ) ? (t + 1) : t;
        float nA0 = zbA[((size_t)tn * BATCH + b0 + 0) * G1D];
        float nA1 = zbA[((size_t)tn * BATCH + b0 + 1) * G1D];
        float nA2 = zbA[((size_t)tn * BATCH + b0 + 2) * G1D];
        float nA3 = zbA[((size_t)tn * BATCH + b0 + 3) * G1D];
        float nB0 = zbB[((size_t)tn * BATCH + b0 + 0) * G1D];
        float nB1 = zbB[((size_t)tn * BATCH + b0 + 1) * G1D];
        float nB2 = zbB[((size_t)tn * BATCH + b0 + 2) * G1D];
        float nB3 = zbB[((size_t)tn * BATCH + b0 + 3) * G1D];

        const float* hp = hT + (t & 1) * (4 * H1P);
        u64 aA0 = 0ull, aA1 = 0ull, aA2 = 0ull, aA3 = 0ull;
        u64 aB0 = 0ull, aB1 = 0ull, aB2 = 0ull, aB3 = 0ull;
#pragma unroll
        for (int p4 = 0; p4 < U1REGJ / 4; ++p4) {
            int j0 = 4 * p4;
            ulonglong2 h0 = *reinterpret_cast<const ulonglong2*>(&hp[0 * H1P + j0]);
            ulonglong2 h1 = *reinterpret_cast<const ulonglong2*>(&hp[1 * H1P + j0]);
            ulonglong2 h2 = *reinterpret_cast<const ulonglong2*>(&hp[2 * H1P + j0]);
            ulonglong2 h3 = *reinterpret_cast<const ulonglong2*>(&hp[3 * H1P + j0]);
            u64 ua = UpA[2 * p4], ub = UpA[2 * p4 + 1];
            u64 va = UpB[2 * p4], vb = UpB[2 * p4 + 1];
            ffma2(aA0, h0.x, ua); ffma2(aA0, h0.y, ub);
            ffma2(aA1, h1.x, ua); ffma2(aA1, h1.y, ub);
            ffma2(aA2, h2.x, ua); ffma2(aA2, h2.y, ub);
            ffma2(aA3, h3.x, ua); ffma2(aA3, h3.y, ub);
            ffma2(aB0, h0.x, va); ffma2(aB0, h0.y, vb);
            ffma2(aB1, h1.x, va); ffma2(aB1, h1.y, vb);
            ffma2(aB2, h2.x, va); ffma2(aB2, h2.y, vb);
            ffma2(aB3, h3.x, va); ffma2(aB3, h3.y, vb);
        }
#pragma unroll
        for (int q = 0; q < U1SMJ / 4; ++q) {
            int j0 = U1REGJ + 4 * q;
            ulonglong2 uA = *reinterpret_cast<const ulonglong2*>(&U1sT[tid * U1SMJ + 4 * q]);
            ulonglong2 uB = *reinterpret_cast<const ulonglong2*>(&U1sT[(256 + tid) * U1SMJ + 4 * q]);
            ulonglong2 h0 = *reinterpret_cast<const ulonglong2*>(&hp[0 * H1P + j0]);
            ulonglong2 h1 = *reinterpret_cast<const ulonglong2*>(&hp[1 * H1P + j0]);
            ulonglong2 h2 = *reinterpret_cast<const ulonglong2*>(&hp[2 * H1P + j0]);
            ulonglong2 h3 = *reinterpret_cast<const ulonglong2*>(&hp[3 * H1P + j0]);
            ffma2(aA0, h0.x, uA.x); ffma2(aA0, h0.y, uA.y);
            ffma2(aA1, h1.x, uA.x); ffma2(aA1, h1.y, uA.y);
            ffma2(aA2, h2.x, uA.x); ffma2(aA2, h2.y, uA.y);
            ffma2(aA3, h3.x, uA.x); ffma2(aA3, h3.y, uA.y);
            ffma2(aB0, h0.x, uB.x); ffma2(aB0, h0.y, uB.y);
            ffma2(aB1, h1.x, uB.x); ffma2(aB1, h1.y, uB.y);
            ffma2(aB2, h2.x, uB.x); ffma2(aB2, h2.y, uB.y);
            ffma2(aB3, h3.x, uB.x); ffma2(aB3, h3.y, uB.y);
        }
        float2 sA0 = unpk(aA0), sA1 = unpk(aA1), sA2 = unpk(aA2), sA3 = unpk(aA3);
        float2 sB0 = unpk(aB0), sB1 = unpk(aB1), sB2 = unpk(aB2), sB3 = unpk(aB3);
        float vA0 = sA0.x + sA0.y + zA0;
        float vA1 = sA1.x + sA1.y + zA1;
        float vA2 = sA2.x + sA2.y + zA2;
        float vA3 = sA3.x + sA3.y + zA3;
        float vB0 = sB0.x + sB0.y + zB0;
        float vB1 = sB1.x + sB1.y + zB1;
        float vB2 = sB2.x + sB2.y + zB2;
        float vB3 = sB3.x + sB3.y + zB3;
        if (k == 2) {
            vA0 = fmaxf(vA0, 0.f); vA1 = fmaxf(vA1, 0.f);
            vA2 = fmaxf(vA2, 0.f); vA3 = fmaxf(vA3, 0.f);
            vB0 = fmaxf(vB0, 0.f); vB1 = fmaxf(vB1, 0.f);
            vB2 = fmaxf(vB2, 0.f); vB3 = fmaxf(vB3, 0.f);
        } else {
            vA0 = fsig(vA0); vA1 = fsig(vA1); vA2 = fsig(vA2); vA3 = fsig(vA3);
            vB0 = fsig(vB0); vB1 = fsig(vB1); vB2 = fsig(vB2); vB3 = fsig(vB3);
        }
        *reinterpret_cast<float4*>(&zs[jA * ZSP + k * 4]) = make_float4(vA0, vA1, vA2, vA3);
        *reinterpret_cast<float4*>(&zs[jB * ZSP + k * 4]) = make_float4(vB0, vB1, vB2, vB3);
        __syncwarp();
        {
            float gi = zs[jA * ZSP + 0  + k];
            float gf = zs[jA * ZSP + 4  + k];
            float gg = zs[jA * ZSP + 8  + k];
            float go = zs[jA * ZSP + 12 + k];
            cA = fmaf(gf, cA, gi * gg);
            float h = go * fmaxf(cA, 0.f);
            hT[(1 - (t & 1)) * (4 * H1P) + k * H1P + jA] = h;
            if (j4 < 50) hout[((size_t)t * BATCH + b0 + k) * H1D + jA] = h;
        }
        {
            float gi = zs[jB * ZSP + 0  + k];
            float gf = zs[jB * ZSP + 4  + k];
            float gg = zs[jB * ZSP + 8  + k];
            float go = zs[jB * ZSP + 12 + k];
            cB = fmaf(gf, cB, gi * gg);
            float h = go * fmaxf(cB, 0.f);
            hT[(1 - (t & 1)) * (4 * H1P) + k * H1P + jB] = h;
            if (j4 < 50) hout[((size_t)t * BATCH + b0 + k) * H1D + jB] = h;
        }
        zA0 = nA0; zA1 = nA1; zA2 = nA2; zA3 = nA3;
        zB0 = nB0; zB1 = nB1; zB2 = nB2; zB3 = nB3;
        __syncthreads();
    }
}

// ---------------- layer-2 scan (R6-proven): 256 threads, 2 cols/thread ------
#define U2REGJ 80
#define U2SMJ  48
#define U2P    52
__global__ __launch_bounds__(256, 1)
void lstm_scan2(const float* __restrict__ zx, const float* __restrict__ U,
                float* __restrict__ h2out)
{
    extern __shared__ __align__(16) float sm2[];
    float* U2sT = sm2;                       // [512 slots][U2P]
    float* hT   = sm2 + 512 * U2P;           // [2][4][H2D]
    float* zs   = hT + 2 * 4 * H2D;          // [128][ZSP]

    const int tid = threadIdx.x;
    const int j  = tid >> 2;        // 0..63
    const int k  = tid & 3;
    const int jA = j, jB = j + 64;
    const int colA = k * H2D + jA;
    const int colB = k * H2D + jB;
    const int b0 = blockIdx.x * 4;

    u64 UpA[U2REGJ / 2], UpB[U2REGJ / 2];
#pragma unroll
    for (int p = 0; p < U2REGJ / 2; ++p) {
        UpA[p] = pack2(U[(2 * p) * G2D + colA], U[(2 * p + 1) * G2D + colA]);
        UpB[p] = pack2(U[(2 * p) * G2D + colB], U[(2 * p + 1) * G2D + colB]);
    }
    for (int idx = tid; idx < U2SMJ * G2D; idx += 256) {
        int r = idx >> 9;
        int cc = idx & 511;
        int jj = cc & 127, kk = cc >> 7;
        int slot = (jj < 64) ? (4 * jj + kk) : (256 + 4 * (jj - 64) + kk);
        U2sT[slot * U2P + r] = U[(size_t)(U2REGJ + r) * G2D + cc];
    }
    for (int i = tid; i < 2 * 4 * H2D; i += 256) hT[i] = 0.f;

    float cA = 0.f, cB = 0.f;
    const float* zbA = zx + colA;
    const float* zbB = zx + colB;
    float zA0 = zbA[((size_t)0 * BATCH + b0 + 0) * G2D];
    float zA1 = zbA[((size_t)0 * BATCH + b0 + 1) * G2D];
    float zA2 = zbA[((size_t)0 * BATCH + b0 + 2) * G2D];
    float zA3 = zbA[((size_t)0 * BATCH + b0 + 3) * G2D];
    float zB0 = zbB[((size_t)0 * BATCH + b0 + 0) * G2D];
    float zB1 = zbB[((size_t)0 * BATCH + b0 + 1) * G2D];
    float zB2 = zbB[((size_t)0 * BATCH + b0 + 2) * G2D];
    float zB3 = zbB[((size_t)0 * BATCH + b0 + 3) * G2D];
    __syncthreads();

#pragma unroll 1
    for (int t = 0; t < T_SEQ; ++t) {
        int tn = (t + 1 < T_SEQ) ? (t + 1) : t;
        float nA0 = zbA[((size_t)tn * BATCH + b0 + 0) * G2D];
        float nA1 = zbA[((size_t)tn * BATCH + b0 + 1) * G2D];
        float nA2 = zbA[((size_t)tn * BATCH + b0 + 2) * G2D];
        float nA3 = zbA[((size_t)tn * BATCH + b0 + 3) * G2D];
        float nB0 = zbB[((size_t)tn * BATCH + b0 + 0) * G2D];
        float nB1 = zbB[((size_t)tn * BATCH + b0 + 1) * G2D];
        float nB2 = zbB[((size_t)tn * BATCH + b0 + 2) * G2D];
        float nB3 = zbB[((size_t)tn * BATCH + b0 + 3) * G2D];

        const float* hp = hT + (t & 1) * (4 * H2D);
        u64 aA0 = 0ull, aA1 = 0ull, aA2 = 0ull, aA3 = 0ull;
        u64 aB0 = 0ull, aB1 = 0ull, aB2 = 0ull, aB3 = 0ull;
#pragma unroll
        for (int p4 = 0; p4 < U2REGJ / 4; ++p4) {
            int j0 = 4 * p4;
            ulonglong2 h0 = *reinterpret_cast<const ulonglong2*>(&hp[0 * H2D + j0]);
            ulonglong2 h1 = *reinterpret_cast<const ulonglong2*>(&hp[1 * H2D + j0]);
            ulonglong2 h2 = *reinterpret_cast<const ulonglong2*>(&hp[2 * H2D + j0]);
            ulonglong2 h3 = *reinterpret_cast<const ulonglong2*>(&hp[3 * H2D + j0]);
            u64 ua = UpA[2 * p4], ub = UpA[2 * p4 + 1];
            u64 va = UpB[2 * p4], vb = UpB[2 * p4 + 1];
            ffma2(aA0, h0.x, ua); ffma2(aA0, h0.y, ub);
            ffma2(aA1, h1.x, ua); ffma2(aA1, h1.y, ub);
            ffma2(aA2, h2.x, ua); ffma2(aA2, h2.y, ub);
            ffma2(aA3, h3.x, ua); ffma2(aA3, h3.y, ub);
            ffma2(aB0, h0.x, va); ffma2(aB0, h0.y, vb);
            ffma2(aB1, h1.x, va); ffma2(aB1, h1.y, vb);
            ffma2(aB2, h2.x, va); ffma2(aB2, h2.y, vb);
            ffma2(aB3, h3.x, va); ffma2(aB3, h3.y, vb);
        }
#pragma unroll
        for (int q = 0; q < U2SMJ / 4; ++q) {
            int j0 = U2REGJ + 4 * q;
            ulonglong2 uA = *reinterpret_cast<const ulonglong2*>(&U2sT[tid * U2P + 4 * q]);
            ulonglong2 uB = *reinterpret_cast<const ulonglong2*>(&U2sT[(256 + tid) * U2P + 4 * q]);
            ulonglong2 h0 = *reinterpret_cast<const ulonglong2*>(&hp[0 * H2D + j0]);
            ulonglong2 h1 = *reinterpret_cast<const ulonglong2*>(&hp[1 * H2D + j0]);
            ulonglong2 h2 = *reinterpret_cast<const ulonglong2*>(&hp[2 * H2D + j0]);
            ulonglong2 h3 = *reinterpret_cast<const ulonglong2*>(&hp[3 * H2D + j0]);
            ffma2(aA0, h0.x, uA.x); ffma2(aA0, h0.y, uA.y);
            ffma2(aA1, h1.x, uA.x); ffma2(aA1, h1.y, uA.y);
            ffma2(aA2, h2.x, uA.x); ffma2(aA2, h2.y, uA.y);
            ffma2(aA3, h3.x, uA.x); ffma2(aA3, h3.y, uA.y);
            ffma2(aB0, h0.x, uB.x); ffma2(aB0, h0.y, uB.y);
            ffma2(aB1, h1.x, uB.x); ffma2(aB1, h1.y, uB.y);
            ffma2(aB2, h2.x, uB.x); ffma2(aB2, h2.y, uB.y);
            ffma2(aB3, h3.x, uB.x); ffma2(aB3, h3.y, uB.y);
        }
        float2 sA0 = unpk(aA0), sA1 = unpk(aA1), sA2 = unpk(aA2), sA3 = unpk(aA3);
        float2 sB0 = unpk(aB0), sB1 = unpk(aB1), sB2 = unpk(aB2), sB3 = unpk(aB3);
        float vA0 = sA0.x + sA0.y + zA0;
        float vA1 = sA1.x + sA1.y + zA1;
        float vA2 = sA2.x + sA2.y + zA2;
        float vA3 = sA3.x + sA3.y + zA3;
        float vB0 = sB0.x + sB0.y + zB0;
        float vB1 = sB1.x + sB1.y + zB1;
        float vB2 = sB2.x + sB2.y + zB2;
        float vB3 = sB3.x + sB3.y + zB3;
        if (k == 2) {
            vA0 = fmaxf(vA0, 0.f); vA1 = fmaxf(vA1, 0.f);
            vA2 = fmaxf(vA2, 0.f); vA3 = fmaxf(vA3, 0.f);
            vB0 = fmaxf(vB0, 0.f); vB1 = fmaxf(vB1, 0.f);
            vB2 = fmaxf(vB2, 0.f); vB3 = fmaxf(vB3, 0.f);
        } else {
            vA0 = fsig(vA0); vA1 = fsig(vA1); vA2 = fsig(vA2); vA3 = fsig(vA3);
            vB0 = fsig(vB0); vB1 = fsig(vB1); vB2 = fsig(vB2); vB3 = fsig(vB3);
        }
        *reinterpret_cast<float4*>(&zs[jA * ZSP + k * 4]) = make_float4(vA0, vA1, vA2, vA3);
        *reinterpret_cast<float4*>(&zs[jB * ZSP + k * 4]) = make_float4(vB0, vB1, vB2, vB3);
        __syncwarp();
        {
            float gi = zs[jA * ZSP + 0  + k];
            float gf = zs[jA * ZSP + 4  + k];
            float gg = zs[jA * ZSP + 8  + k];
            float go = zs[jA * ZSP + 12 + k];
            cA = fmaf(gf, cA, gi * gg);
            float h = go * fmaxf(cA, 0.f);
            hT[(1 - (t & 1)) * (4 * H2D) + k * H2D + jA] = h;
            if (t == T_SEQ - 1) h2out[(b0 + k) * H2D + jA] = h;
        }
        {
            float gi = zs[jB * ZSP + 0  + k];
            float gf = zs[jB * ZSP + 4  + k];
            float gg = zs[jB * ZSP + 8  + k];
            float go = zs[jB * ZSP + 12 + k];
            cB = fmaf(gf, cB, gi * gg);
            float h = go * fmaxf(cB, 0.f);
            hT[(1 - (t & 1)) * (4 * H2D) + k * H2D + jB] = h;
            if (t == T_SEQ - 1) h2out[(b0 + k) * H2D + jB] = h;
        }
        zA0 = nA0; zA1 = nA1; zA2 = nA2; zA3 = nA3;
        zB0 = nB0; zB1 = nB1; zB2 = nB2; zB3 = nB3;
        __syncthreads();
    }
}

// ---------------- dense head + softmax -------------------------------------
__global__ void head_kernel(const float* __restrict__ h2, const float* __restrict__ Wd,
                            const float* __restrict__ bd, float* __restrict__ out)
{
    __shared__ float hsh[H2D];
    const int b = blockIdx.x;
    const int lane = threadIdx.x;
    for (int j = lane; j < H2D; j += 32) hsh[j] = h2[b * H2D + j];
    __syncthreads();

    float acc = 0.f;
    if (lane < NC) {
        acc = bd[lane];
#pragma unroll
        for (int j = 0; j < H2D; ++j) acc = fmaf(hsh[j], Wd[j * NC + lane], acc);
    }
    float v = (lane < NC) ? acc : -FLT_MAX;
#pragma unroll
    for (int off = 16; off > 0; off >>= 1)
        v = fmaxf(v, __shfl_xor_sync(0xffffffffu, v, off));
    float e = (lane < NC) ? expf(acc - v) : 0.f;
    float s = e;
#pragma unroll
    for (int off = 16; off > 0; off >>= 1)
        s += __shfl_xor_sync(0xffffffffu, s, off);
    if (lane < NC) out[b * NC + lane] = e / s;
}

// ---------------- launch ----------------------------------------------------
extern "C" void kernel_launch(void* const* d_in, const int* in_sizes, int n_in,
                              void* d_out, int out_size)
{
    const float* x  = (const float*)d_in[0];
    const float* W1 = (const float*)d_in[1];
    const float* U1 = (const float*)d_in[2];
    const float* b1 = (const float*)d_in[3];
    const float* W2 = (const float*)d_in[4];
    const float* U2 = (const float*)d_in[5];
    const float* b2 = (const float*)d_in[6];
    const float* Wd = (const float*)d_in[7];
    const float* bd = (const float*)d_in[8];
    float* out = (float*)d_out;

    const int gemm_smem  = (KMAX * AP + KMAX * BN) * 4;                    // 67584
    const int scan1_smem = (512 * U1SMJ + 2 * 4 * H1P + 128 * ZSP) * 4;    // 54528
    const int scan2_smem = (512 * U2P + 2 * 4 * H2D + 128 * ZSP) * 4;      // 120832
    cudaFuncSetAttribute(gemm_ff,    cudaFuncAttributeMaxDynamicSharedMemorySize, gemm_smem);
    cudaFuncSetAttribute(lstm_scan1, cudaFuncAttributeMaxDynamicSharedMemorySize, scan1_smem);
    cudaFuncSetAttribute(lstm_scan2, cudaFuncAttributeMaxDynamicSharedMemorySize, scan2_smem);

    float *zx1p, *h1p, *zx2p, *h2p;
    cudaGetSymbolAddress((void**)&zx1p, g_zx1);
    cudaGetSymbolAddress((void**)&h1p,  g_h1);
    cudaGetSymbolAddress((void**)&zx2p, g_zx2);
    cudaGetSymbolAddress((void**)&h2p,  g_h2);

    const int M = T_SEQ * BATCH;

    gemm_ff<<<M / BM, 256, gemm_smem>>>(x, W1, b1, zx1p, M, G1D, IND, 1);

    lstm_scan1<<<BATCH / 4, 256, scan1_smem>>>(zx1p, U1, h1p);

    gemm_ff<<<M / BM, 256, gemm_smem>>>(h1p, W2, b2, zx2p, M, G2D, H1D, 0);

    lstm_scan2<<<BATCH / 4, 256, scan2_smem>>>(zx2p, U2, h2p);

    head_kernel<<<BATCH, 32>>>(h2p, Wd, bd, out);
}